// round 16
// baseline (speedup 1.0000x reference)
#include <cuda_runtime.h>
#include <cuda_fp16.h>
#include <cstddef>

#define N_USER  100000
#define N_ITEM  50000
#define N_NODES 150000
#define EMB     64
#define N_EDGES 4000000
#define BATCH   4096
#define PW_INV_LAYERS 0.25f   // 1/(N_LAYERS+1)
#define TB 256
#define NBLK ((N_NODES + TB - 1) / TB)   // 586 scan blocks

// ---- device-global scratch (allocation-free) ----
__device__ __half g_c0[(size_t)N_NODES * EMB];
__device__ __half g_c1[(size_t)N_NODES * EMB];
__device__ __half g_c2[(size_t)N_NODES * EMB];
__device__ int    g_cnt   [N_NODES];        // zero-init; re-zeroed by k_scan3
__device__ int    g_fill  [N_NODES];
__device__ int    g_rowptr[N_NODES + 1];
__device__ int    g_bsum  [1024];
__device__ int2   g_perm  [N_EDGES];        // (col, val as duplicated half2) 32 MB

// ---------------------------------------------------------------------------
// init + hist fused (R10-validated scalar version)
// ---------------------------------------------------------------------------
__global__ void k_init_hist(const float* __restrict__ ue,
                            const float* __restrict__ ie,
                            const int*   __restrict__ rows) {
    int i = blockIdx.x * blockDim.x + threadIdx.x;
    if (i < N_EDGES)
        atomicAdd(&g_cnt[__ldg(rows + i)], 1);
    if (i < N_NODES * 32) {
        const float2* u2 = (const float2*)ue;
        const float2* i2 = (const float2*)ie;
        float2 v = (i < N_USER * 32) ? u2[i] : i2[i - N_USER * 32];
        ((half2*)g_c0)[i] = __floats2half2_rn(v.x, v.y);
    }
}

// ---------------------------------------------------------------------------
// CSR scan a: per-block sums
// ---------------------------------------------------------------------------
__global__ void k_scan1() {
    __shared__ int sh[TB];
    int i = blockIdx.x * TB + threadIdx.x;
    int c = (i < N_NODES) ? g_cnt[i] : 0;
    sh[threadIdx.x] = c; __syncthreads();
    for (int off = TB / 2; off > 0; off >>= 1) {
        if (threadIdx.x < off) sh[threadIdx.x] += sh[threadIdx.x + off];
        __syncthreads();
    }
    if (threadIdx.x == 0) g_bsum[blockIdx.x] = sh[0];
}

// ---------------------------------------------------------------------------
// CSR scan b: exclusive scan of block sums (single block)
// ---------------------------------------------------------------------------
__global__ void k_scan2() {
    __shared__ int sh[1024];
    int t = threadIdx.x;
    int v = (t < NBLK) ? g_bsum[t] : 0;
    sh[t] = v; __syncthreads();
    for (int off = 1; off < 1024; off <<= 1) {
        int add = (t >= off) ? sh[t - off] : 0;
        __syncthreads();
        sh[t] += add;
        __syncthreads();
    }
    if (t < NBLK) g_bsum[t] = sh[t] - v;   // exclusive
}

// ---------------------------------------------------------------------------
// CSR scan c: row_ptr + fill cursors; re-zeroes g_cnt for next replay
// ---------------------------------------------------------------------------
__global__ void k_scan3() {
    __shared__ int sh[TB];
    int i = blockIdx.x * TB + threadIdx.x;
    int c = (i < N_NODES) ? g_cnt[i] : 0;
    sh[threadIdx.x] = c; __syncthreads();
    for (int off = 1; off < TB; off <<= 1) {
        int add = (threadIdx.x >= off) ? sh[threadIdx.x - off] : 0;
        __syncthreads();
        sh[threadIdx.x] += add;
        __syncthreads();
    }
    int excl = sh[threadIdx.x] - c + g_bsum[blockIdx.x];
    if (i < N_NODES) { g_rowptr[i] = excl; g_fill[i] = excl; g_cnt[i] = 0; }
    if (i == 0) g_rowptr[N_NODES] = N_EDGES;
}

// ---------------------------------------------------------------------------
// CSR build: fill-cursor permute (R10-validated)
// ---------------------------------------------------------------------------
__global__ void k_permute(const int*   __restrict__ rows,
                          const int*   __restrict__ cols,
                          const float* __restrict__ vals) {
    int e = blockIdx.x * blockDim.x + threadIdx.x;
    if (e >= N_EDGES) return;
    int r = __ldg(rows + e);
    int idx = atomicAdd(&g_fill[r], 1);
    unsigned h = (unsigned)__half_as_ushort(__float2half_rn(__ldg(vals + e)));
    g_perm[idx] = make_int2(__ldg(cols + e), (int)(h * 0x10001u));
}

// ---------------------------------------------------------------------------
// Warp-level row accumulation, QUARTER-warp edition:
// - stage 32 (col, half2-val) entries in the warp's smem slab (as R10/R15)
// - FIXED 8-trip fully-unrolled loop; the four 8-lane QUARTERS each process
//   one edge per trip: lane owns a 16B slice (sub=lane&7) of its edge's row
//   -> per 4 edges: 1 LDS.64 + 1 LDG.128 + 4 HFMA2 (LDG count halved vs R15)
// - per-lane 4x half2 accumulators, flushed to fp32 per chunk;
//   2-stage shfl_xor(8,16) combine once at the end
// - pad entries (0,0): gather L1-hot row 0 with weight 0 (validated scheme)
// Returns 8 fp32 sums (halves [8*sub, 8*sub+8)) valid in all lanes.
// ---------------------------------------------------------------------------
struct F8 { float4 a, b; };

__device__ __forceinline__ F8 row_accumulate(const __half* __restrict__ src,
                                             int beg, int end, int lane,
                                             int2* __restrict__ slab) {
    int qw  = lane >> 3;       // quarter index (selects edge of the quad)
    int sub = lane & 7;        // 16B slice index within the row
    float f[8];
    #pragma unroll
    for (int k = 0; k < 8; k++) f[k] = 0.f;

    for (int base = beg; base < end; base += 32) {
        int n = end - base;
        int2 ev = make_int2(0, 0);
        if (lane < n) ev = __ldg(&g_perm[base + lane]);
        __syncwarp();
        slab[lane] = ev;
        __syncwarp();
        half2 a0 = __float2half2_rn(0.f);
        half2 a1 = a0, a2 = a0, a3 = a0;
        #pragma unroll
        for (int j = 0; j < 8; j++) {
            int2 e = slab[4 * j + qw];
            half2 v = *(half2*)&e.y;
            int4 xi = *((const int4*)(src + (size_t)e.x * EMB) + sub);
            a0 = __hfma2(v, *(half2*)&xi.x, a0);
            a1 = __hfma2(v, *(half2*)&xi.y, a1);
            a2 = __hfma2(v, *(half2*)&xi.z, a2);
            a3 = __hfma2(v, *(half2*)&xi.w, a3);
        }
        float2 f0 = __half22float2(a0);
        float2 f1 = __half22float2(a1);
        float2 f2 = __half22float2(a2);
        float2 f3 = __half22float2(a3);
        f[0] += f0.x; f[1] += f0.y; f[2] += f1.x; f[3] += f1.y;
        f[4] += f2.x; f[5] += f2.y; f[6] += f3.x; f[7] += f3.y;
        __syncwarp();
    }
    // combine the four quarters' partial sums (each covered its own edges)
    #pragma unroll
    for (int k = 0; k < 8; k++) {
        f[k] += __shfl_xor_sync(0xffffffffu, f[k], 8);
        f[k] += __shfl_xor_sync(0xffffffffu, f[k], 16);
    }
    F8 r;
    r.a = make_float4(f[0], f[1], f[2], f[3]);
    r.b = make_float4(f[4], f[5], f[6], f[7]);
    return r;
}

// ---------------------------------------------------------------------------
// full layer: one warp per row, atomic-free pull
// ---------------------------------------------------------------------------
template <int APPLY_POP>
__global__ void __launch_bounds__(TB)
k_layer(const __half* __restrict__ src,
        __half*       __restrict__ dst,
        const float*  __restrict__ upi,
        const float*  __restrict__ ipi) {
    __shared__ __align__(16) int2 sh[TB / 32][32];
    int gid  = blockIdx.x * blockDim.x + threadIdx.x;
    int row  = gid >> 5;
    int lane = gid & 31;
    int wid  = threadIdx.x >> 5;
    if (row >= N_NODES) return;

    int beg = __ldg(&g_rowptr[row]);
    int end = __ldg(&g_rowptr[row + 1]);

    F8 s = row_accumulate(src, beg, end, lane, sh[wid]);

    if (APPLY_POP) {
        float sc = (row < N_USER) ? __ldg(upi + row) : __ldg(ipi + (row - N_USER));
        s.a.x *= sc; s.a.y *= sc; s.a.z *= sc; s.a.w *= sc;
        s.b.x *= sc; s.b.y *= sc; s.b.z *= sc; s.b.w *= sc;
    }

    if (lane < 8) {
        half2 h0 = __floats2half2_rn(s.a.x, s.a.y);
        half2 h1 = __floats2half2_rn(s.a.z, s.a.w);
        half2 h2 = __floats2half2_rn(s.b.x, s.b.y);
        half2 h3 = __floats2half2_rn(s.b.z, s.b.w);
        int4 pk = make_int4(*(int*)&h0, *(int*)&h1, *(int*)&h2, *(int*)&h3);
        ((int4*)(dst + (size_t)row * EMB))[lane] = pk;   // lane==sub here
    }
}

// ---------------------------------------------------------------------------
// fused layer-3 + gather: one warp per batch slot; c3 computed in registers
// for the ~12K sampled rows only.
//   out[sec]   = 0.25*(emb + pw*(c1+c2+c3))   sec 0..2
//   out[3+sec] = emb
// lanes 0-7 each own 8 floats (two float4) of the 64-float row.
// ---------------------------------------------------------------------------
__global__ void __launch_bounds__(TB)
k_l3_gather(const float* __restrict__ ue,
            const float* __restrict__ ie,
            const float* __restrict__ pwp,
            const int*   __restrict__ users,
            const int*   __restrict__ pos,
            const int*   __restrict__ neg,
            float* __restrict__ out) {
    __shared__ __align__(16) int2 sh[TB / 32][32];
    int gid  = blockIdx.x * blockDim.x + threadIdx.x;
    int w    = gid >> 5;
    int lane = gid & 31;
    int wid  = threadIdx.x >> 5;
    if (w >= 3 * BATCH) return;
    int sec = w / BATCH;
    int b   = w - sec * BATCH;

    int node; const float* emb;
    if (sec == 0)      { int u = __ldg(users + b); node = u;          emb = ue + (size_t)u * EMB; }
    else if (sec == 1) { int p = __ldg(pos + b);   node = N_USER + p; emb = ie + (size_t)p * EMB; }
    else               { int p = __ldg(neg + b);   node = N_USER + p; emb = ie + (size_t)p * EMB; }

    int beg = __ldg(&g_rowptr[node]);
    int end = __ldg(&g_rowptr[node + 1]);
    F8 s = row_accumulate(g_c2, beg, end, lane, sh[wid]);

    if (lane < 8) {
        float pw = __ldg(pwp);
        int sub = lane;
        float4 e0 = ((const float4*)emb)[2 * sub];
        float4 e1 = ((const float4*)emb)[2 * sub + 1];
        int4 c1i = *((const int4*)(g_c1 + (size_t)node * EMB) + sub);
        int4 c2i = *((const int4*)(g_c2 + (size_t)node * EMB) + sub);
        float2 c1f[4] = { __half22float2(*(half2*)&c1i.x), __half22float2(*(half2*)&c1i.y),
                          __half22float2(*(half2*)&c1i.z), __half22float2(*(half2*)&c1i.w) };
        float2 c2f[4] = { __half22float2(*(half2*)&c2i.x), __half22float2(*(half2*)&c2i.y),
                          __half22float2(*(half2*)&c2i.z), __half22float2(*(half2*)&c2i.w) };

        float4 o0, o1;
        o0.x = PW_INV_LAYERS * (e0.x + pw * (c1f[0].x + c2f[0].x + s.a.x));
        o0.y = PW_INV_LAYERS * (e0.y + pw * (c1f[0].y + c2f[0].y + s.a.y));
        o0.z = PW_INV_LAYERS * (e0.z + pw * (c1f[1].x + c2f[1].x + s.a.z));
        o0.w = PW_INV_LAYERS * (e0.w + pw * (c1f[1].y + c2f[1].y + s.a.w));
        o1.x = PW_INV_LAYERS * (e1.x + pw * (c1f[2].x + c2f[2].x + s.b.x));
        o1.y = PW_INV_LAYERS * (e1.y + pw * (c1f[2].y + c2f[2].y + s.b.y));
        o1.z = PW_INV_LAYERS * (e1.z + pw * (c1f[3].x + c2f[3].x + s.b.z));
        o1.w = PW_INV_LAYERS * (e1.w + pw * (c1f[3].y + c2f[3].y + s.b.w));

        size_t slot = (size_t)b * 16 + 2 * sub;   // float4 index within section
        ((float4*)out)[(size_t)sec * BATCH * 16 + slot]           = o0;
        ((float4*)out)[(size_t)sec * BATCH * 16 + slot + 1]       = o1;
        ((float4*)out)[(size_t)(3 + sec) * BATCH * 16 + slot]     = e0;
        ((float4*)out)[(size_t)(3 + sec) * BATCH * 16 + slot + 1] = e1;
    }
}

// ---------------------------------------------------------------------------
// kernel_launch
// Inputs: user_emb, item_emb, edge_rows, edge_cols, edge_vals,
//         user_pop_inv, item_pop_inv, popularity_weight, users, pos, neg
// ---------------------------------------------------------------------------
extern "C" void kernel_launch(void* const* d_in, const int* in_sizes, int n_in,
                              void* d_out, int out_size) {
    const float* ue    = (const float*)d_in[0];
    const float* ie    = (const float*)d_in[1];
    const int*   erow  = (const int*)  d_in[2];
    const int*   ecol  = (const int*)  d_in[3];
    const float* eval_ = (const float*)d_in[4];
    const float* upi   = (const float*)d_in[5];
    const float* ipi   = (const float*)d_in[6];
    const float* pwp   = (const float*)d_in[7];
    const int*   users = (const int*)  d_in[8];
    const int*   pos   = (const int*)  d_in[9];
    const int*   neg   = (const int*)  d_in[10];
    float* out = (float*)d_out;

    __half *c0, *c1, *c2;
    cudaGetSymbolAddress((void**)&c0, g_c0);
    cudaGetSymbolAddress((void**)&c1, g_c1);
    cudaGetSymbolAddress((void**)&c2, g_c2);

    const int inith_grid    = (N_NODES * 32 + TB - 1) / TB;   // covers 4M edges too
    const int edge_grid     = (N_EDGES + TB - 1) / TB;
    const int row_warp_grid = (N_NODES * 32 + TB - 1) / TB;   // 1 warp/row
    const int l3g_grid      = (3 * BATCH * 32 + TB - 1) / TB;

    // init + CSR build (every replay; deterministic; R10-validated config)
    k_init_hist<<<inith_grid, TB>>>(ue, ie, erow);
    k_scan1<<<NBLK, TB>>>();
    k_scan2<<<1, 1024>>>();
    k_scan3<<<NBLK, TB>>>();
    k_permute<<<edge_grid, TB>>>(erow, ecol, eval_);

    // layers 1 and 2 over all nodes (quarter-warp HFMA2 core)
    k_layer<1><<<row_warp_grid, TB>>>(c0, c1, upi, ipi);
    k_layer<0><<<row_warp_grid, TB>>>(c1, c2, upi, ipi);

    // layer 3 restricted to sampled rows, fused with output gather
    k_l3_gather<<<l3g_grid, TB>>>(ue, ie, pwp, users, pos, neg, out);

    (void)in_sizes; (void)n_in; (void)out_size;
}

// round 17
// speedup vs baseline: 1.2021x; 1.2021x over previous
#include <cuda_runtime.h>
#include <cuda_fp16.h>
#include <cstddef>

#define N_USER  100000
#define N_ITEM  50000
#define N_NODES 150000
#define EMB     64
#define N_EDGES 4000000
#define BATCH   4096
#define PW_INV_LAYERS 0.25f   // 1/(N_LAYERS+1)
#define TB 256
#define NBLK ((N_NODES + TB - 1) / TB)   // 586 scan blocks

// ---- device-global scratch (allocation-free) ----
__device__ __half g_c0[(size_t)N_NODES * EMB];
__device__ __half g_c1[(size_t)N_NODES * EMB];
__device__ __half g_c2[(size_t)N_NODES * EMB];
__device__ int    g_cnt   [N_NODES];        // zero-init; re-zeroed by k_scan3
__device__ int    g_fill  [N_NODES];
__device__ int    g_rowptr[N_NODES + 1];
__device__ int    g_bsum  [1024];
__device__ int2   g_perm  [N_EDGES];        // (col, val as duplicated half2) 32 MB

// ---------------------------------------------------------------------------
// init + hist fused:
// - hist part: scalar 1 edge/thread (R10-validated; vectorizing THIS part
//   regressed in R9)
// - c0 part: one thread per float4 (2.4M threads): LDG.128 + STG.64
// ---------------------------------------------------------------------------
__global__ void k_init_hist(const float* __restrict__ ue,
                            const float* __restrict__ ie,
                            const int*   __restrict__ rows) {
    int i = blockIdx.x * blockDim.x + threadIdx.x;
    if (i < N_EDGES)
        atomicAdd(&g_cnt[__ldg(rows + i)], 1);
    if (i < N_NODES * 16) {
        const float4* u4 = (const float4*)ue;
        const float4* i4 = (const float4*)ie;
        float4 v = (i < N_USER * 16) ? u4[i] : i4[i - N_USER * 16];
        half2 h0 = __floats2half2_rn(v.x, v.y);
        half2 h1 = __floats2half2_rn(v.z, v.w);
        ((int2*)g_c0)[i] = make_int2(*(int*)&h0, *(int*)&h1);
    }
}

// ---------------------------------------------------------------------------
// CSR scan a: per-block sums
// ---------------------------------------------------------------------------
__global__ void k_scan1() {
    __shared__ int sh[TB];
    int i = blockIdx.x * TB + threadIdx.x;
    int c = (i < N_NODES) ? g_cnt[i] : 0;
    sh[threadIdx.x] = c; __syncthreads();
    for (int off = TB / 2; off > 0; off >>= 1) {
        if (threadIdx.x < off) sh[threadIdx.x] += sh[threadIdx.x + off];
        __syncthreads();
    }
    if (threadIdx.x == 0) g_bsum[blockIdx.x] = sh[0];
}

// ---------------------------------------------------------------------------
// CSR scan b: exclusive scan of block sums (single block)
// ---------------------------------------------------------------------------
__global__ void k_scan2() {
    __shared__ int sh[1024];
    int t = threadIdx.x;
    int v = (t < NBLK) ? g_bsum[t] : 0;
    sh[t] = v; __syncthreads();
    for (int off = 1; off < 1024; off <<= 1) {
        int add = (t >= off) ? sh[t - off] : 0;
        __syncthreads();
        sh[t] += add;
        __syncthreads();
    }
    if (t < NBLK) g_bsum[t] = sh[t] - v;   // exclusive
}

// ---------------------------------------------------------------------------
// CSR scan c: row_ptr + fill cursors; re-zeroes g_cnt for next replay
// ---------------------------------------------------------------------------
__global__ void k_scan3() {
    __shared__ int sh[TB];
    int i = blockIdx.x * TB + threadIdx.x;
    int c = (i < N_NODES) ? g_cnt[i] : 0;
    sh[threadIdx.x] = c; __syncthreads();
    for (int off = 1; off < TB; off <<= 1) {
        int add = (threadIdx.x >= off) ? sh[threadIdx.x - off] : 0;
        __syncthreads();
        sh[threadIdx.x] += add;
        __syncthreads();
    }
    int excl = sh[threadIdx.x] - c + g_bsum[blockIdx.x];
    if (i < N_NODES) { g_rowptr[i] = excl; g_fill[i] = excl; g_cnt[i] = 0; }
    if (i == 0) g_rowptr[N_NODES] = N_EDGES;
}

// ---------------------------------------------------------------------------
// CSR build: fill-cursor permute (R10-validated)
// ---------------------------------------------------------------------------
__global__ void k_permute(const int*   __restrict__ rows,
                          const int*   __restrict__ cols,
                          const float* __restrict__ vals) {
    int e = blockIdx.x * blockDim.x + threadIdx.x;
    if (e >= N_EDGES) return;
    int r = __ldg(rows + e);
    int idx = atomicAdd(&g_fill[r], 1);
    unsigned h = (unsigned)__half_as_ushort(__float2half_rn(__ldg(vals + e)));
    g_perm[idx] = make_int2(__ldg(cols + e), (int)(h * 0x10001u));
}

// ---------------------------------------------------------------------------
// Warp-level row accumulation, half-warp-paired (R15-validated optimum):
// - stage 32 (col, half2-val) entries in the warp's smem slab
// - FIXED 16-trip fully-unrolled loop; the two HALF-WARPS process two
//   different edges per trip: lane owns an 8B slice (sub=lane&15)
//   -> per 2 edges: 1 LDS.64 + 1 LDG.64 + 2 HFMA2
// - per-lane half2 accumulators, flushed to fp32 per chunk;
//   one shfl_xor(16) combine at the end
// - pad entries (0,0): gather L1-hot row 0 with weight 0
// Returns float4 = fp32 sums for halves [4*sub, 4*sub+4) (valid all lanes).
// ---------------------------------------------------------------------------
__device__ __forceinline__ float4 row_accumulate(const __half* __restrict__ src,
                                                 int beg, int end, int lane,
                                                 int2* __restrict__ slab) {
    int hw  = lane >> 4;       // which half-warp (selects edge of the pair)
    int sub = lane & 15;       // 8B slice index within the row
    float2 s0 = make_float2(0.f, 0.f);
    float2 s1 = make_float2(0.f, 0.f);
    for (int base = beg; base < end; base += 32) {
        int n = end - base;
        int2 ev = make_int2(0, 0);
        if (lane < n) ev = __ldg(&g_perm[base + lane]);
        __syncwarp();
        slab[lane] = ev;
        __syncwarp();
        half2 a0 = __float2half2_rn(0.f);
        half2 a1 = __float2half2_rn(0.f);
        #pragma unroll
        for (int j = 0; j < 16; j++) {
            int2 e = slab[2 * j + hw];
            half2 v = *(half2*)&e.y;
            int2 xi = *((const int2*)(src + (size_t)e.x * EMB) + sub);
            half2 x0 = *(half2*)&xi.x;
            half2 x1 = *(half2*)&xi.y;
            a0 = __hfma2(v, x0, a0);
            a1 = __hfma2(v, x1, a1);
        }
        float2 f0 = __half22float2(a0);
        float2 f1 = __half22float2(a1);
        s0.x += f0.x; s0.y += f0.y;
        s1.x += f1.x; s1.y += f1.y;
        __syncwarp();
    }
    // combine the two half-warps' partial sums (each covered its own edges)
    s0.x += __shfl_xor_sync(0xffffffffu, s0.x, 16);
    s0.y += __shfl_xor_sync(0xffffffffu, s0.y, 16);
    s1.x += __shfl_xor_sync(0xffffffffu, s1.x, 16);
    s1.y += __shfl_xor_sync(0xffffffffu, s1.y, 16);
    return make_float4(s0.x, s0.y, s1.x, s1.y);
}

// ---------------------------------------------------------------------------
// full layer: one warp per row, atomic-free pull
// ---------------------------------------------------------------------------
template <int APPLY_POP>
__global__ void __launch_bounds__(TB)
k_layer(const __half* __restrict__ src,
        __half*       __restrict__ dst,
        const float*  __restrict__ upi,
        const float*  __restrict__ ipi) {
    __shared__ __align__(16) int2 sh[TB / 32][32];
    int gid  = blockIdx.x * blockDim.x + threadIdx.x;
    int row  = gid >> 5;
    int lane = gid & 31;
    int wid  = threadIdx.x >> 5;
    if (row >= N_NODES) return;

    int beg = __ldg(&g_rowptr[row]);
    int end = __ldg(&g_rowptr[row + 1]);

    float4 s = row_accumulate(src, beg, end, lane, sh[wid]);

    if (APPLY_POP) {
        float sc = (row < N_USER) ? __ldg(upi + row) : __ldg(ipi + (row - N_USER));
        s.x *= sc; s.y *= sc; s.z *= sc; s.w *= sc;
    }

    if (lane < 16) {
        half2 h0 = __floats2half2_rn(s.x, s.y);
        half2 h1 = __floats2half2_rn(s.z, s.w);
        int2 pk = make_int2(*(int*)&h0, *(int*)&h1);
        ((int2*)(dst + (size_t)row * EMB))[lane] = pk;   // lane==sub here
    }
}

// ---------------------------------------------------------------------------
// fused layer-3 + gather: one warp per batch slot; c3 computed in registers
// for the ~12K sampled rows only.
//   out[sec]   = 0.25*(emb + pw*(c1+c2+c3))   sec 0..2
//   out[3+sec] = emb
// lanes 0-15 each own a float4 (4 floats) slice of the 64-float row.
// ---------------------------------------------------------------------------
__global__ void __launch_bounds__(TB)
k_l3_gather(const float* __restrict__ ue,
            const float* __restrict__ ie,
            const float* __restrict__ pwp,
            const int*   __restrict__ users,
            const int*   __restrict__ pos,
            const int*   __restrict__ neg,
            float* __restrict__ out) {
    __shared__ __align__(16) int2 sh[TB / 32][32];
    int gid  = blockIdx.x * blockDim.x + threadIdx.x;
    int w    = gid >> 5;
    int lane = gid & 31;
    int wid  = threadIdx.x >> 5;
    if (w >= 3 * BATCH) return;
    int sec = w / BATCH;
    int b   = w - sec * BATCH;

    int node; const float* emb;
    if (sec == 0)      { int u = __ldg(users + b); node = u;          emb = ue + (size_t)u * EMB; }
    else if (sec == 1) { int p = __ldg(pos + b);   node = N_USER + p; emb = ie + (size_t)p * EMB; }
    else               { int p = __ldg(neg + b);   node = N_USER + p; emb = ie + (size_t)p * EMB; }

    int beg = __ldg(&g_rowptr[node]);
    int end = __ldg(&g_rowptr[node + 1]);
    float4 s = row_accumulate(g_c2, beg, end, lane, sh[wid]);

    if (lane < 16) {
        float pw = __ldg(pwp);
        int sub = lane;
        float4 e4 = ((const float4*)emb)[sub];
        int2 c1i = *((const int2*)(g_c1 + (size_t)node * EMB) + sub);
        int2 c2i = *((const int2*)(g_c2 + (size_t)node * EMB) + sub);
        float2 c1a = __half22float2(*(half2*)&c1i.x);
        float2 c1b = __half22float2(*(half2*)&c1i.y);
        float2 c2a = __half22float2(*(half2*)&c2i.x);
        float2 c2b = __half22float2(*(half2*)&c2i.y);

        float4 o;
        o.x = PW_INV_LAYERS * (e4.x + pw * (c1a.x + c2a.x + s.x));
        o.y = PW_INV_LAYERS * (e4.y + pw * (c1a.y + c2a.y + s.y));
        o.z = PW_INV_LAYERS * (e4.z + pw * (c1b.x + c2b.x + s.z));
        o.w = PW_INV_LAYERS * (e4.w + pw * (c1b.y + c2b.y + s.w));

        size_t slot = (size_t)b * 16 + sub;
        ((float4*)out)[(size_t)sec * BATCH * 16 + slot]       = o;   // sections 0-2
        ((float4*)out)[(size_t)(3 + sec) * BATCH * 16 + slot] = e4;  // sections 3-5
    }
}

// ---------------------------------------------------------------------------
// kernel_launch
// Inputs: user_emb, item_emb, edge_rows, edge_cols, edge_vals,
//         user_pop_inv, item_pop_inv, popularity_weight, users, pos, neg
// ---------------------------------------------------------------------------
extern "C" void kernel_launch(void* const* d_in, const int* in_sizes, int n_in,
                              void* d_out, int out_size) {
    const float* ue    = (const float*)d_in[0];
    const float* ie    = (const float*)d_in[1];
    const int*   erow  = (const int*)  d_in[2];
    const int*   ecol  = (const int*)  d_in[3];
    const float* eval_ = (const float*)d_in[4];
    const float* upi   = (const float*)d_in[5];
    const float* ipi   = (const float*)d_in[6];
    const float* pwp   = (const float*)d_in[7];
    const int*   users = (const int*)  d_in[8];
    const int*   pos   = (const int*)  d_in[9];
    const int*   neg   = (const int*)  d_in[10];
    float* out = (float*)d_out;

    __half *c0, *c1, *c2;
    cudaGetSymbolAddress((void**)&c0, g_c0);
    cudaGetSymbolAddress((void**)&c1, g_c1);
    cudaGetSymbolAddress((void**)&c2, g_c2);

    const int inith_grid    = (N_EDGES + TB - 1) / TB;        // 4M > 2.4M c0-quads
    const int edge_grid     = (N_EDGES + TB - 1) / TB;
    const int row_warp_grid = (N_NODES * 32 + TB - 1) / TB;   // 1 warp/row
    const int l3g_grid      = (3 * BATCH * 32 + TB - 1) / TB;

    // init + CSR build (every replay; deterministic; R10-validated config)
    k_init_hist<<<inith_grid, TB>>>(ue, ie, erow);
    k_scan1<<<NBLK, TB>>>();
    k_scan2<<<1, 1024>>>();
    k_scan3<<<NBLK, TB>>>();
    k_permute<<<edge_grid, TB>>>(erow, ecol, eval_);

    // layers 1 and 2 over all nodes (half-warp-paired HFMA2 core, R15)
    k_layer<1><<<row_warp_grid, TB>>>(c0, c1, upi, ipi);
    k_layer<0><<<row_warp_grid, TB>>>(c1, c2, upi, ipi);

    // layer 3 restricted to sampled rows, fused with output gather
    k_l3_gather<<<l3g_grid, TB>>>(ue, ie, pwp, users, pos, neg, out);

    (void)in_sizes; (void)n_in; (void)out_size;
}